// round 16
// baseline (speedup 1.0000x reference)
#include <cuda_runtime.h>
#include <math.h>

#define HH 192
#define WWID 192
#define HW 36864
#define DIM 96
#define NHW 47
#define NWW 95
#define NWIN 4465

typedef unsigned long long ull;

// ---------------- scratch ----------------
__device__ float2 g_win[NWIN*3072];      // per-window av output [win][n(32)][ch(96)]
__device__ float2 g_y_p[DIM*HW];
__device__ float2 g_t_p[DIM*HW];
__device__ float g_stats1[4*DIM];
__device__ float g_stats2[4*DIM];
__device__ float g_bn1[4*DIM];
__device__ float g_bn2[4*DIM];
__device__ float2 g_qkv_p[288*HW];
__device__ float2 g_hid[384*HW];

// packed weights float2 {wr, wi}
#define QOFF  0
#define POFF  27648
#define W1OFF 36864
#define W2OFF 73728
#define NWTOT 110592
__device__ float2 g_wf2[NWTOT];

// ---------------- packed f32x2 helpers ----------------
__device__ __forceinline__ ull pki(unsigned lo, unsigned hi) {
    ull r; asm("mov.b64 %0, {%1, %2};" : "=l"(r) : "r"(lo), "r"(hi)); return r;
}
__device__ __forceinline__ ull pkf(float lo, float hi) {
    ull r; asm("mov.b64 %0, {%1, %2};" : "=l"(r) : "f"(lo), "f"(hi)); return r;
}
__device__ __forceinline__ void fma2(ull& d, ull a, ull b) {
    asm("fma.rn.f32x2 %0, %1, %2, %0;" : "+l"(d) : "l"(a), "l"(b));
}
__device__ __forceinline__ float2 upk(ull v) {
    float2 f; asm("mov.b64 {%0, %1}, %2;" : "=f"(f.x), "=f"(f.y) : "l"(v)); return f;
}
__device__ __forceinline__ float2 cmb(ull S, ull T) {
    float2 s = upk(S), t = upk(T);
    return make_float2(s.x - t.x, s.y + t.y);
}

// stage 4 outputs x 96 channels of float2 weights into warp slot
__device__ __forceinline__ void stage96f2(const float2* __restrict__ src, float2* dst, int lane) {
    #pragma unroll
    for (int i = 0; i < 12; i++) dst[lane + 32*i] = src[lane + 32*i];
}

// dual-pixel dual-acc complex GEMM over 96 channels, 4 outputs (R11 scheme).
__device__ __forceinline__ void gemm96_2p(const float* sm, int xbase, int n,
                                          const float2* ws, ull S[8], ull T[8]) {
    const float4* x4 = (const float4*)(sm + xbase);
    #pragma unroll 2
    for (int c = 0; c < 96; c += 2) {
        float4 xv0 = x4[c*32 + n];
        float4 xv1 = x4[(c+1)*32 + n];
        ull Pa0 = pkf(xv0.x, xv0.y), Qa0 = pkf(xv0.y, xv0.x);
        ull Pb0 = pkf(xv0.z, xv0.w), Qb0 = pkf(xv0.w, xv0.z);
        ull Pa1 = pkf(xv1.x, xv1.y), Qa1 = pkf(xv1.y, xv1.x);
        ull Pb1 = pkf(xv1.z, xv1.w), Qb1 = pkf(xv1.w, xv1.z);
        #pragma unroll
        for (int l = 0; l < 4; l++) {
            float4 wv = *(const float4*)(ws + l*96 + c);
            ull wr0 = pkf(wv.x, wv.x), wi0 = pkf(wv.y, wv.y);
            ull wr1 = pkf(wv.z, wv.z), wi1 = pkf(wv.w, wv.w);
            fma2(S[l],   wr0, Pa0); fma2(T[l],   wi0, Qa0);
            fma2(S[4+l], wr0, Pb0); fma2(T[4+l], wi0, Qb0);
            fma2(S[l],   wr1, Pa1); fma2(T[l],   wi1, Qa1);
            fma2(S[4+l], wr1, Pb1); fma2(T[4+l], wi1, Qb1);
        }
    }
}

// ---------------- weight pre-pack ----------------
__global__ void k_pack(const float* __restrict__ qwr, const float* __restrict__ qwi,
                       const float* __restrict__ pwr, const float* __restrict__ pwi,
                       const float* __restrict__ w1r, const float* __restrict__ w1i,
                       const float* __restrict__ w2r, const float* __restrict__ w2i) {
    int idx = blockIdx.x*256 + threadIdx.x;
    if (idx >= NWTOT) return;
    const float *wr, *wi; int j;
    if (idx < POFF)       { wr = qwr; wi = qwi; j = idx; }
    else if (idx < W1OFF) { wr = pwr; wi = pwi; j = idx - POFF; }
    else if (idx < W2OFF) { wr = w1r; wi = w1i; j = idx - W1OFF; }
    else                  { wr = w2r; wi = w2i; j = idx - W2OFF; }
    g_wf2[idx] = make_float2(wr[j], wi[j]);
}

// ---------------- pixel-level qkv GEMM (64 pixels / block) ----------------
#define QKV_SMEM (21504*4)
__global__ __launch_bounds__(384, 2) void k_qkv(
    const float* __restrict__ xr, const float* __restrict__ xi)
{
    extern __shared__ float sm[];
    const int SXP = 9216;
    int tid = threadIdx.x;
    int p0 = blockIdx.x * 64;
    int n = tid & 31, og = tid >> 5;
    float2* wslot = (float2*)sm + og*384;

    for (int idx = tid; idx < 6144; idx += 384) {
        int g = (idx >> 6)*HW + p0 + (idx & 63);
        ((float2*)(sm + SXP))[idx] = make_float2(xr[g], xi[g]);
    }
    __syncthreads();

    for (int ch = 0; ch < 6; ch++) {
        int o0 = og*24 + ch*4;
        __syncwarp();
        stage96f2(g_wf2 + QOFF + o0*96, wslot, n);
        __syncwarp();
        ull S[8] = {0,0,0,0,0,0,0,0}, T[8] = {0,0,0,0,0,0,0,0};
        gemm96_2p(sm, SXP, n, wslot, S, T);
        #pragma unroll
        for (int l = 0; l < 4; l++) {
            float2 a = cmb(S[l], T[l]);
            float2 b = cmb(S[4+l], T[4+l]);
            ((float4*)(g_qkv_p + (o0+l)*HW + p0))[n] = make_float4(a.x, a.y, b.x, b.y);
        }
    }
}

// ---------------- window attention middle (2 heads per block) ----------------
// smem floats: q[0,2048) k[2048,4096) v[4096,6144) attn [6144,10496) rows pad 34
#define AT_SMEM (10496*4)
__global__ __launch_bounds__(256, 4) void k_attnmid(const float* __restrict__ rel)
{
    extern __shared__ float sm[];
    const int SQ = 0, SK = 2048, SV = 4096, SA = 6144;
    int tid = threadIdx.x;
    int blk = blockIdx.x;
    int win = blk / 3, hg = blk - win*3;
    int wi = win / NWW, wj = win - wi*NWW;
    int h0 = wi*4, w0 = wj*2;
    int cbase = hg*32;

    for (int idx = tid; idx < 3*1024; idx += 256) {
        int t = idx >> 10, r = idx & 1023;
        int c = r >> 5, nn = r & 31;
        int g = (t*96 + cbase + c)*HW + (h0 + (nn>>2))*WWID + w0 + (nn&3);
        ((float2*)(sm))[t*1024 + c*32 + nn] = g_qkv_p[g];
    }
    __syncthreads();

    #pragma unroll 2
    for (int it = 0; it < 4; it++) {
        int e = tid + 256*it;
        int hh = e >> 9;
        int r = e & 511;
        int nn = r >> 4, mm2 = (r & 15) << 1;
        float acr0 = 0.f, aci0 = 0.f, acr1 = 0.f, aci1 = 0.f;
        #pragma unroll
        for (int d = 0; d < 16; d++) {
            float2 qp = ((float2*)(sm + SQ))[(hh*16+d)*32 + nn];
            float4 kv = *(const float4*)((float2*)(sm + SK) + (hh*16+d)*32 + mm2);
            acr0 += qp.x*kv.x + qp.y*kv.y;
            aci0 += qp.y*kv.x - qp.x*kv.y;
            acr1 += qp.x*kv.z + qp.y*kv.w;
            aci1 += qp.y*kv.z - qp.x*kv.w;
        }
        acr0 *= 0.25f; aci0 *= 0.25f;
        acr1 *= 0.25f; aci1 *= 0.25f;
        int an = nn>>2, bn = nn&3;
        int am0 = mm2>>2, bm0 = mm2&3;
        int am1 = (mm2+1)>>2, bm1 = (mm2+1)&3;
        const float* rb = rel + (hg*2 + hh)*105;
        acr0 += rb[7*(an - am0 + 7) + (bn - bm0 + 3)];
        acr1 += rb[7*(an - am1 + 7) + (bn - bm1 + 3)];
        float4* ap = (float4*)((float2*)(sm + SA) + (hh*32 + nn)*34 + mm2);
        ap[0] = make_float4(acr0, aci0, acr1, aci1);
    }
    __syncthreads();

    if (tid < 128) {
        int row = tid >> 1, half = tid & 1;
        float2* rp = (float2*)(sm + SA) + row*34 + half*16;
        float mg[16];
        float mx = -1e30f;
        #pragma unroll
        for (int m = 0; m < 16; m++) {
            float2 a = rp[m];
            mg[m] = sqrtf(a.x*a.x + a.y*a.y);
            mx = fmaxf(mx, mg[m]);
        }
        mx = fmaxf(mx, __shfl_xor_sync(0xffffffffu, mx, 1));
        float s = 0.f;
        #pragma unroll
        for (int m = 0; m < 16; m++) s += __expf(mg[m] - mx);
        s += __shfl_xor_sync(0xffffffffu, s, 1);
        float inv = 1.0f / s;
        #pragma unroll
        for (int m = 0; m < 16; m++) {
            float f = __expf(mg[m] - mx)*inv / (mg[m] + 1e-8f);
            float2 a = rp[m];
            rp[m] = make_float2(a.x*f, a.y*f);
        }
    }
    __syncthreads();

    // out = attn @ v -> direct store to g_win (no atomics)
    if (tid < 128) {
        int hh = tid >> 6, r = tid & 63, nn = r >> 1, oh = (r & 1)*8;
        const float2* arow = (const float2*)(sm + SA) + (hh*32 + nn)*34;
        const uint2* vp = (const uint2*)(sm + SV);
        float2* dstbase = g_win + (ull)win*3072 + nn*96 + cbase + hh*16;
        #pragma unroll
        for (int chk = 0; chk < 2; chk++) {
            int ob = oh + chk*4;
            ull acc[4] = {0,0,0,0};
            #pragma unroll 4
            for (int m = 0; m < 32; m++) {
                float2 a = arow[m];
                ull dar = pkf(a.x, a.x);
                ull dai = pkf(-a.y, a.y);
                #pragma unroll
                for (int o = 0; o < 4; o++) {
                    uint2 v = vp[(hh*16 + ob + o)*32 + m];
                    fma2(acc[o], dar, pki(v.x, v.y));
                    fma2(acc[o], dai, pki(v.y, v.x));
                }
            }
            float2 f0 = upk(acc[0]), f1 = upk(acc[1]);
            float2 f2 = upk(acc[2]), f3 = upk(acc[3]);
            ((float4*)(dstbase + ob))[0] = make_float4(f0.x, f0.y, f1.x, f1.y);
            ((float4*)(dstbase + ob))[1] = make_float4(f2.x, f2.y, f3.x, f3.y);
        }
    }
}

// ---------------- proj(gathered win sums / count) + x residual, BN1 stats --
#define CPROJ_SMEM (21504*4)
__global__ __launch_bounds__(384, 2) void k_cproj(
    const float* __restrict__ xr, const float* __restrict__ xi)
{
    extern __shared__ float sm[];
    __shared__ int s_off[64][4];
    __shared__ float s_inv[64];
    const int SXP = 9216;
    int tid = threadIdx.x;
    int p0 = blockIdx.x * 64;
    int n = tid & 31, og = tid >> 5;
    float2* wslot = (float2*)sm + og*384;

    // per-pixel contributing-window offsets (win*3072 + n*96), -1 if absent
    if (tid < 64) {
        int p = p0 + tid;
        int h = p / WWID, w = p - h*WWID;
        int wilo = (h >= 7) ? ((h-4) >> 2) : 0;
        int wihi = min(46, h >> 2);
        int wjlo = (w >= 3) ? ((w-2) >> 1) : 0;
        int wjhi = min(94, w >> 1);
        int cnt = (wihi - wilo + 1)*(wjhi - wjlo + 1);
        s_inv[tid] = 1.0f / ((float)cnt + 1e-8f);
        int k = 0;
        for (int a = wilo; a <= wihi; a++)
            for (int b = wjlo; b <= wjhi; b++) {
                int npos = (h - 4*a)*4 + (w - 2*b);
                s_off[tid][k++] = (a*NWW + b)*3072 + npos*96;
            }
        for (; k < 4; k++) s_off[tid][k] = -1;
    }
    __syncthreads();

    for (int idx = tid; idx < 6144; idx += 384) {
        int c = idx >> 6, pp = idx & 63;
        float2 acc = make_float2(0.f, 0.f);
        #pragma unroll
        for (int k = 0; k < 4; k++) {
            int off = s_off[pp][k];
            if (off >= 0) {
                float2 v = g_win[off + c];
                acc.x += v.x; acc.y += v.y;
            }
        }
        float inv = s_inv[pp];
        ((float2*)(sm + SXP))[idx] = make_float2(acc.x*inv, acc.y*inv);
    }
    __syncthreads();

    for (int ch = 0; ch < 2; ch++) {
        int o0 = og*8 + ch*4;
        __syncwarp();
        stage96f2(g_wf2 + POFF + o0*96, wslot, n);
        __syncwarp();
        ull S[8] = {0,0,0,0,0,0,0,0}, T[8] = {0,0,0,0,0,0,0,0};
        gemm96_2p(sm, SXP, n, wslot, S, T);
        #pragma unroll
        for (int l = 0; l < 4; l++) {
            int o = o0 + l;
            int g = o*HW + p0 + 2*n;
            float2 a = cmb(S[l], T[l]);
            float2 b = cmb(S[4+l], T[4+l]);
            float2 y0 = make_float2(xr[g]   + a.x, xi[g]   + a.y);
            float2 y1 = make_float2(xr[g+1] + b.x, xi[g+1] + b.y);
            ((float4*)(g_y_p + g))[0] = make_float4(y0.x, y0.y, y1.x, y1.y);
            float v0 = y0.x + y1.x, v1 = y0.x*y0.x + y1.x*y1.x;
            float v2 = y0.y + y1.y, v3 = y0.y*y0.y + y1.y*y1.y;
            #pragma unroll
            for (int off = 16; off; off >>= 1) {
                v0 += __shfl_xor_sync(0xffffffffu, v0, off);
                v1 += __shfl_xor_sync(0xffffffffu, v1, off);
                v2 += __shfl_xor_sync(0xffffffffu, v2, off);
                v3 += __shfl_xor_sync(0xffffffffu, v3, off);
            }
            if (n == 0) {
                atomicAdd(&g_stats1[o], v0);
                atomicAdd(&g_stats1[96+o], v1);
                atomicAdd(&g_stats1[192+o], v2);
                atomicAdd(&g_stats1[288+o], v3);
            }
        }
    }
}

// ---------------- finalize BN params ----------------
__global__ void k_bnfin(int which,
    const float* __restrict__ gr, const float* __restrict__ br,
    const float* __restrict__ gi, const float* __restrict__ bi)
{
    int c = threadIdx.x;
    if (c >= DIM) return;
    const float* s = which ? g_stats2 : g_stats1;
    float* o = which ? g_bn2 : g_bn1;
    const float invN = 1.0f / (float)HW;
    float mu = s[c]*invN;
    float var = s[96+c]*invN - mu*mu;
    float sc = gr[c]*rsqrtf(var + 1e-5f);
    o[c] = sc; o[96+c] = br[c] - mu*sc;
    mu = s[192+c]*invN;
    var = s[288+c]*invN - mu*mu;
    sc = gi[c]*rsqrtf(var + 1e-5f);
    o[192+c] = sc; o[288+c] = bi[c] - mu*sc;
}

// ---------------- mlp1: BN1-apply + GEMM + cgelu -> g_hid (64 px) ----------
#define MLP1_SMEM (21888*4)
__global__ __launch_bounds__(384, 2) void k_mlp1()
{
    extern __shared__ float sm[];
    const int SXP = 9216, SBN = 21504;
    int tid = threadIdx.x;
    int p0 = blockIdx.x * 64;
    int n = tid & 31, og = tid >> 5;
    float2* wslot = (float2*)sm + og*384;

    if (tid < 384) sm[SBN + tid] = g_bn1[tid];
    __syncthreads();

    for (int idx = tid; idx < 6144; idx += 384) {
        int c = idx >> 6, pp = idx & 63;
        float2 yp = g_y_p[c*HW + p0 + pp];
        ((float2*)(sm + SXP))[idx] = make_float2(
            yp.x*sm[SBN + c]       + sm[SBN + 96 + c],
            yp.y*sm[SBN + 192 + c] + sm[SBN + 288 + c]);
    }
    __syncthreads();

    for (int ch = 0; ch < 8; ch++) {
        int o0 = og*32 + ch*4;
        __syncwarp();
        stage96f2(g_wf2 + W1OFF + o0*96, wslot, n);
        __syncwarp();
        ull S[8] = {0,0,0,0,0,0,0,0}, T[8] = {0,0,0,0,0,0,0,0};
        gemm96_2p(sm, SXP, n, wslot, S, T);
        #pragma unroll
        for (int l = 0; l < 4; l++) {
            float2 a = cmb(S[l], T[l]);
            float2 b = cmb(S[4+l], T[4+l]);
            float mga = sqrtf(a.x*a.x + a.y*a.y);
            float fa = 0.5f*mga*(1.0f + erff(mga*0.70710678118654752f)) / (mga + 1e-8f);
            float mgb = sqrtf(b.x*b.x + b.y*b.y);
            float fb = 0.5f*mgb*(1.0f + erff(mgb*0.70710678118654752f)) / (mgb + 1e-8f);
            ((float4*)(g_hid + (o0+l)*HW + p0))[n] =
                make_float4(a.x*fa, a.y*fa, b.x*fb, b.y*fb);
        }
    }
}

// ---------------- mlp2: hidden GEMM + residual + BN2 stats (64 px) --------
#define MLP2_SMEM (21888*4)
__global__ __launch_bounds__(384, 2) void k_mlp2()
{
    extern __shared__ float sm[];
    const int SH = 9216, SBN = 21504;
    int tid = threadIdx.x;
    int p0 = blockIdx.x * 64;
    int n = tid & 31, og = tid >> 5;
    float2* wslot = (float2*)sm + og*384;

    if (tid < 384) sm[SBN + tid] = g_bn1[tid];

    for (int ch = 0; ch < 2; ch++) {
        int o0 = og*8 + ch*4;
        ull S[8] = {0,0,0,0,0,0,0,0}, T[8] = {0,0,0,0,0,0,0,0};
        for (int cb = 0; cb < 4; cb++) {
            __syncthreads();
            for (int idx = tid; idx < 6144; idx += 384) {
                int c = idx >> 6, pp = idx & 63;
                ((float2*)(sm + SH))[idx] = g_hid[(cb*96 + c)*HW + p0 + pp];
            }
            const float2* src = g_wf2 + W2OFF + o0*384 + cb*96;
            #pragma unroll
            for (int l = 0; l < 4; l++)
                for (int i = n; i < 96; i += 32) wslot[l*96 + i] = src[l*384 + i];
            __syncthreads();
            gemm96_2p(sm, SH, n, wslot, S, T);
        }
        #pragma unroll
        for (int l = 0; l < 4; l++) {
            int o = o0 + l;
            int g = o*HW + p0 + 2*n;
            float2 a = cmb(S[l], T[l]);
            float2 b = cmb(S[4+l], T[4+l]);
            float4 yv = ((const float4*)(g_y_p + g))[0];
            float scr = sm[SBN + o], shr = sm[SBN + 96 + o];
            float sci = sm[SBN + 192 + o], shi = sm[SBN + 288 + o];
            float2 t0 = make_float2(yv.x*scr + shr + a.x, yv.y*sci + shi + a.y);
            float2 t1 = make_float2(yv.z*scr + shr + b.x, yv.w*sci + shi + b.y);
            ((float4*)(g_t_p + g))[0] = make_float4(t0.x, t0.y, t1.x, t1.y);
            float v0 = t0.x + t1.x, v1 = t0.x*t0.x + t1.x*t1.x;
            float v2 = t0.y + t1.y, v3 = t0.y*t0.y + t1.y*t1.y;
            #pragma unroll
            for (int off = 16; off; off >>= 1) {
                v0 += __shfl_xor_sync(0xffffffffu, v0, off);
                v1 += __shfl_xor_sync(0xffffffffu, v1, off);
                v2 += __shfl_xor_sync(0xffffffffu, v2, off);
                v3 += __shfl_xor_sync(0xffffffffu, v3, off);
            }
            if (n == 0) {
                atomicAdd(&g_stats2[o], v0);
                atomicAdd(&g_stats2[96+o], v1);
                atomicAdd(&g_stats2[192+o], v2);
                atomicAdd(&g_stats2[288+o], v3);
            }
        }
    }
}

// ---------------- BN2-apply -> output ----------------
__global__ void k_out(float* __restrict__ out) {
    int idx = blockIdx.x*256 + threadIdx.x;
    if (idx >= DIM*HW) return;
    int c = idx / HW;
    float2 t = g_t_p[idx];
    out[idx]           = t.x*g_bn2[c]     + g_bn2[96+c];
    out[DIM*HW + idx]  = t.y*g_bn2[192+c] + g_bn2[288+c];
}

// ---------------- launch ----------------
extern "C" void kernel_launch(void* const* d_in, const int* in_sizes, int n_in,
                              void* d_out, int out_size)
{
    const float* xr   = (const float*)d_in[0];
    const float* xi   = (const float*)d_in[1];
    const float* qwr  = (const float*)d_in[2];
    const float* qwi  = (const float*)d_in[3];
    const float* pwr  = (const float*)d_in[4];
    const float* pwi  = (const float*)d_in[5];
    const float* rel  = (const float*)d_in[6];
    const float* w1r  = (const float*)d_in[7];
    const float* w1i  = (const float*)d_in[8];
    const float* w2r  = (const float*)d_in[9];
    const float* w2i  = (const float*)d_in[10];
    const float* n1gr = (const float*)d_in[11];
    const float* n1br = (const float*)d_in[12];
    const float* n1gi = (const float*)d_in[13];
    const float* n1bi = (const float*)d_in[14];
    const float* n2gr = (const float*)d_in[15];
    const float* n2br = (const float*)d_in[16];
    const float* n2gi = (const float*)d_in[17];
    const float* n2bi = (const float*)d_in[18];

    cudaFuncSetAttribute(k_qkv,     cudaFuncAttributeMaxDynamicSharedMemorySize, QKV_SMEM);
    cudaFuncSetAttribute(k_attnmid, cudaFuncAttributeMaxDynamicSharedMemorySize, AT_SMEM);
    cudaFuncSetAttribute(k_cproj,   cudaFuncAttributeMaxDynamicSharedMemorySize, CPROJ_SMEM);
    cudaFuncSetAttribute(k_mlp1,    cudaFuncAttributeMaxDynamicSharedMemorySize, MLP1_SMEM);
    cudaFuncSetAttribute(k_mlp2,    cudaFuncAttributeMaxDynamicSharedMemorySize, MLP2_SMEM);

    void *ps1, *ps2;
    cudaGetSymbolAddress(&ps1, g_stats1);
    cudaGetSymbolAddress(&ps2, g_stats2);
    cudaMemsetAsync(ps1, 0, sizeof(float)*4*DIM);
    cudaMemsetAsync(ps2, 0, sizeof(float)*4*DIM);

    k_pack<<<(NWTOT + 255)/256, 256>>>(qwr, qwi, pwr, pwi, w1r, w1i, w2r, w2i);
    k_qkv<<<HW/64, 384, QKV_SMEM>>>(xr, xi);
    k_attnmid<<<3*NWIN, 256, AT_SMEM>>>(rel);
    k_cproj<<<HW/64, 384, CPROJ_SMEM>>>(xr, xi);
    k_bnfin<<<1, 128>>>(0, n1gr, n1br, n1gi, n1bi);
    k_mlp1<<<HW/64, 384, MLP1_SMEM>>>();
    k_mlp2<<<HW/64, 384, MLP2_SMEM>>>();
    k_bnfin<<<1, 128>>>(1, n2gr, n2br, n2gi, n2bi);
    k_out<<<(DIM*HW + 255)/256, 256>>>((float*)d_out);
}

// round 17
// speedup vs baseline: 1.1014x; 1.1014x over previous
#include <cuda_runtime.h>
#include <math.h>

#define HH 192
#define WWID 192
#define HW 36864
#define DIM 96
#define NHW 47
#define NWW 95
#define NWIN 4465

typedef unsigned long long ull;

// ---------------- scratch ----------------
__device__ float2 g_fold_p[DIM*HW];
__device__ float2 g_y_p[DIM*HW];
__device__ float2 g_t_p[DIM*HW];
__device__ float g_stats1[4*DIM];
__device__ float g_stats2[4*DIM];
__device__ float g_bn1[4*DIM];
__device__ float g_bn2[4*DIM];
__device__ float2 g_qkv_p[288*HW];
__device__ float2 g_hid[384*HW];

// packed weights float2 {wr, wi}
#define QOFF  0
#define POFF  27648
#define W1OFF 36864
#define W2OFF 73728
#define NWTOT 110592
__device__ float2 g_wf2[NWTOT];

// ---------------- packed f32x2 helpers ----------------
__device__ __forceinline__ ull pki(unsigned lo, unsigned hi) {
    ull r; asm("mov.b64 %0, {%1, %2};" : "=l"(r) : "r"(lo), "r"(hi)); return r;
}
__device__ __forceinline__ ull pkf(float lo, float hi) {
    ull r; asm("mov.b64 %0, {%1, %2};" : "=l"(r) : "f"(lo), "f"(hi)); return r;
}
__device__ __forceinline__ void fma2(ull& d, ull a, ull b) {
    asm("fma.rn.f32x2 %0, %1, %2, %0;" : "+l"(d) : "l"(a), "l"(b));
}
__device__ __forceinline__ float2 upk(ull v) {
    float2 f; asm("mov.b64 {%0, %1}, %2;" : "=f"(f.x), "=f"(f.y) : "l"(v)); return f;
}
__device__ __forceinline__ float2 cmb(ull S, ull T) {
    float2 s = upk(S), t = upk(T);
    return make_float2(s.x - t.x, s.y + t.y);
}

// stage 4 outputs x 96 channels of float2 weights into warp slot
__device__ __forceinline__ void stage96f2(const float2* __restrict__ src, float2* dst, int lane) {
    #pragma unroll
    for (int i = 0; i < 12; i++) dst[lane + 32*i] = src[lane + 32*i];
}

// dual-pixel dual-acc complex GEMM over 96 channels, 4 outputs (R11 scheme).
__device__ __forceinline__ void gemm96_2p(const float* sm, int xbase, int n,
                                          const float2* ws, ull S[8], ull T[8]) {
    const float4* x4 = (const float4*)(sm + xbase);
    #pragma unroll 2
    for (int c = 0; c < 96; c += 2) {
        float4 xv0 = x4[c*32 + n];
        float4 xv1 = x4[(c+1)*32 + n];
        ull Pa0 = pkf(xv0.x, xv0.y), Qa0 = pkf(xv0.y, xv0.x);
        ull Pb0 = pkf(xv0.z, xv0.w), Qb0 = pkf(xv0.w, xv0.z);
        ull Pa1 = pkf(xv1.x, xv1.y), Qa1 = pkf(xv1.y, xv1.x);
        ull Pb1 = pkf(xv1.z, xv1.w), Qb1 = pkf(xv1.w, xv1.z);
        #pragma unroll
        for (int l = 0; l < 4; l++) {
            float4 wv = *(const float4*)(ws + l*96 + c);
            ull wr0 = pkf(wv.x, wv.x), wi0 = pkf(wv.y, wv.y);
            ull wr1 = pkf(wv.z, wv.z), wi1 = pkf(wv.w, wv.w);
            fma2(S[l],   wr0, Pa0); fma2(T[l],   wi0, Qa0);
            fma2(S[4+l], wr0, Pb0); fma2(T[4+l], wi0, Qb0);
            fma2(S[l],   wr1, Pa1); fma2(T[l],   wi1, Qa1);
            fma2(S[4+l], wr1, Pb1); fma2(T[4+l], wi1, Qb1);
        }
    }
}

// ---------------- weight pre-pack ----------------
__global__ void k_pack(const float* __restrict__ qwr, const float* __restrict__ qwi,
                       const float* __restrict__ pwr, const float* __restrict__ pwi,
                       const float* __restrict__ w1r, const float* __restrict__ w1i,
                       const float* __restrict__ w2r, const float* __restrict__ w2i) {
    int idx = blockIdx.x*256 + threadIdx.x;
    if (idx >= NWTOT) return;
    const float *wr, *wi; int j;
    if (idx < POFF)       { wr = qwr; wi = qwi; j = idx; }
    else if (idx < W1OFF) { wr = pwr; wi = pwi; j = idx - POFF; }
    else if (idx < W2OFF) { wr = w1r; wi = w1i; j = idx - W1OFF; }
    else                  { wr = w2r; wi = w2i; j = idx - W2OFF; }
    g_wf2[idx] = make_float2(wr[j], wi[j]);
}

// ---------------- pixel-level qkv GEMM (64 pixels / block) ----------------
#define QKV_SMEM (21504*4)
__global__ __launch_bounds__(384, 2) void k_qkv(
    const float* __restrict__ xr, const float* __restrict__ xi)
{
    extern __shared__ float sm[];
    const int SXP = 9216;
    int tid = threadIdx.x;
    int p0 = blockIdx.x * 64;
    int n = tid & 31, og = tid >> 5;
    float2* wslot = (float2*)sm + og*384;

    // 2px per thread: float2 loads from xr/xi, interleave into float4 pairs
    for (int idx = tid; idx < 3072; idx += 384) {
        int c = idx >> 5, pp2 = (idx & 31) << 1;
        int g = c*HW + p0 + pp2;
        float2 rr = *(const float2*)(xr + g);
        float2 ii = *(const float2*)(xi + g);
        ((float4*)(sm + SXP))[idx] = make_float4(rr.x, ii.x, rr.y, ii.y);
    }
    __syncthreads();

    for (int ch = 0; ch < 6; ch++) {
        int o0 = og*24 + ch*4;
        __syncwarp();
        stage96f2(g_wf2 + QOFF + o0*96, wslot, n);
        __syncwarp();
        ull S[8] = {0,0,0,0,0,0,0,0}, T[8] = {0,0,0,0,0,0,0,0};
        gemm96_2p(sm, SXP, n, wslot, S, T);
        #pragma unroll
        for (int l = 0; l < 4; l++) {
            float2 a = cmb(S[l], T[l]);
            float2 b = cmb(S[4+l], T[4+l]);
            ((float4*)(g_qkv_p + (o0+l)*HW + p0))[n] = make_float4(a.x, a.y, b.x, b.y);
        }
    }
}

// ---------------- window attention middle (3 heads per block) ----------------
// smem floats: q[0,3072) k[3072,6144) v[6144,9216) attn rows padded to 34 float2
#define AT_SMEM (15744*4)
__global__ __launch_bounds__(256, 3) void k_attnmid(const float* __restrict__ rel)
{
    extern __shared__ float sm[];
    const int SQ = 0, SK = 3072, SV = 6144, SA = 9216;
    int tid = threadIdx.x;
    int blk = blockIdx.x;
    int win = blk >> 1, hg = blk & 1;
    int wi = win / NWW, wj = win - wi*NWW;
    int h0 = wi*4, w0 = wj*2;
    int cbase = hg*48;

    // gather q,k,v: 2 adjacent positions per thread via one LDG.128
    for (int idx = tid; idx < 2304; idx += 256) {
        int t = idx / 768, r = idx - t*768;
        int c = r >> 4, nn2 = (r & 15) << 1;
        int g = (t*96 + cbase + c)*HW + (h0 + (nn2 >> 2))*WWID + w0 + (nn2 & 3);
        float4 v = *(const float4*)(g_qkv_p + g);
        ((float4*)sm)[(t*1536 + c*32 + nn2) >> 1] = v;
    }
    __syncthreads();

    // attn = 0.25 * q . conj(k) + bias : 2 columns per thread, k via LDS.128
    #pragma unroll 2
    for (int it = 0; it < 6; it++) {
        int e = tid + 256*it;             // 0..1535
        int hh = e >> 9;
        int r = e & 511;
        int nn = r >> 4, mm2 = (r & 15) << 1;
        float acr0 = 0.f, aci0 = 0.f, acr1 = 0.f, aci1 = 0.f;
        #pragma unroll
        for (int d = 0; d < 16; d++) {
            float2 qp = ((float2*)(sm + SQ))[(hh*16+d)*32 + nn];
            float4 kv = *(const float4*)((float2*)(sm + SK) + (hh*16+d)*32 + mm2);
            acr0 += qp.x*kv.x + qp.y*kv.y;
            aci0 += qp.y*kv.x - qp.x*kv.y;
            acr1 += qp.x*kv.z + qp.y*kv.w;
            aci1 += qp.y*kv.z - qp.x*kv.w;
        }
        acr0 *= 0.25f; aci0 *= 0.25f;
        acr1 *= 0.25f; aci1 *= 0.25f;
        int an = nn>>2, bn = nn&3;
        int am0 = mm2>>2, bm0 = mm2&3;
        int am1 = (mm2+1)>>2, bm1 = (mm2+1)&3;
        const float* rb = rel + (hg*3 + hh)*105;
        acr0 += rb[7*(an - am0 + 7) + (bn - bm0 + 3)];
        acr1 += rb[7*(an - am1 + 7) + (bn - bm1 + 3)];
        float4* ap = (float4*)((float2*)(sm + SA) + (hh*32 + nn)*34 + mm2);
        ap[0] = make_float4(acr0, aci0, acr1, aci1);
    }
    __syncthreads();

    // magnitude softmax & rescale: 192 threads, 2 per row
    if (tid < 192) {
        int row = tid >> 1, half = tid & 1;
        float2* rp = (float2*)(sm + SA) + row*34 + half*16;
        float mg[16];
        float mx = -1e30f;
        #pragma unroll
        for (int m = 0; m < 16; m++) {
            float2 a = rp[m];
            mg[m] = sqrtf(a.x*a.x + a.y*a.y);
            mx = fmaxf(mx, mg[m]);
        }
        mx = fmaxf(mx, __shfl_xor_sync(0xffffffffu, mx, 1));
        float s = 0.f;
        #pragma unroll
        for (int m = 0; m < 16; m++) s += __expf(mg[m] - mx);
        s += __shfl_xor_sync(0xffffffffu, s, 1);
        float inv = 1.0f / s;
        #pragma unroll
        for (int m = 0; m < 16; m++) {
            float f = __expf(mg[m] - mx)*inv / (mg[m] + 1e-8f);
            float2 a = rp[m];
            rp[m] = make_float2(a.x*f, a.y*f);
        }
    }
    __syncthreads();

    // out = attn @ v, fold with vector atomics
    if (tid < 192) {
        int hh = tid >> 6, r = tid & 63, nn = r >> 1, oh = (r & 1)*8;
        const float2* arow = (const float2*)(sm + SA) + (hh*32 + nn)*34;
        const uint2* vp = (const uint2*)(sm + SV);
        int gpix = (h0 + (nn>>2))*WWID + w0 + (nn&3);
        #pragma unroll
        for (int chk = 0; chk < 2; chk++) {
            int ob = oh + chk*4;
            ull acc[4] = {0,0,0,0};
            #pragma unroll 4
            for (int m = 0; m < 32; m++) {
                float2 a = arow[m];
                ull dar = pkf(a.x, a.x);
                ull dai = pkf(-a.y, a.y);
                #pragma unroll
                for (int o = 0; o < 4; o++) {
                    uint2 v = vp[(hh*16 + ob + o)*32 + m];
                    fma2(acc[o], dar, pki(v.x, v.y));
                    fma2(acc[o], dai, pki(v.y, v.x));
                }
            }
            #pragma unroll
            for (int o = 0; o < 4; o++) {
                float2 f = upk(acc[o]);
                int ch = cbase + hh*16 + ob + o;
                atomicAdd(&g_fold_p[ch*HW + gpix], f);
            }
        }
    }
}

// ---------------- proj(fold/count) + x residual, BN1 stats (64 px) --------
#define CPROJ_SMEM (21504*4)
__global__ __launch_bounds__(384, 2) void k_cproj(
    const float* __restrict__ xr, const float* __restrict__ xi)
{
    extern __shared__ float sm[];
    const int SXP = 9216;
    int tid = threadIdx.x;
    int p0 = blockIdx.x * 64;
    int n = tid & 31, og = tid >> 5;
    float2* wslot = (float2*)sm + og*384;

    // 2px per thread: float4 fold load
    for (int idx = tid; idx < 3072; idx += 384) {
        int c = idx >> 5, pp2 = (idx & 31) << 1;
        float inv[2];
        #pragma unroll
        for (int u = 0; u < 2; u++) {
            int p = p0 + pp2 + u;
            int h = p / WWID, w = p - h*WWID;
            int loh = max(h-7, 0), hih = min(h, 184);
            int cnt_h = hih/4 - (loh+3)/4 + 1;
            int low = max(w-3, 0), hiw = min(w, 188);
            int cnt_w = hiw/2 - (low+1)/2 + 1;
            inv[u] = 1.0f / ((float)(cnt_h*cnt_w) + 1e-8f);
        }
        float4 fp = *(const float4*)(g_fold_p + c*HW + p0 + pp2);
        ((float4*)(sm + SXP))[idx] = make_float4(fp.x*inv[0], fp.y*inv[0], fp.z*inv[1], fp.w*inv[1]);
    }
    __syncthreads();

    for (int ch = 0; ch < 2; ch++) {
        int o0 = og*8 + ch*4;
        __syncwarp();
        stage96f2(g_wf2 + POFF + o0*96, wslot, n);
        __syncwarp();
        ull S[8] = {0,0,0,0,0,0,0,0}, T[8] = {0,0,0,0,0,0,0,0};
        gemm96_2p(sm, SXP, n, wslot, S, T);
        #pragma unroll
        for (int l = 0; l < 4; l++) {
            int o = o0 + l;
            int g = o*HW + p0 + 2*n;
            float2 a = cmb(S[l], T[l]);
            float2 b = cmb(S[4+l], T[4+l]);
            float2 rr = *(const float2*)(xr + g);
            float2 ii = *(const float2*)(xi + g);
            float2 y0 = make_float2(rr.x + a.x, ii.x + a.y);
            float2 y1 = make_float2(rr.y + b.x, ii.y + b.y);
            ((float4*)(g_y_p + g))[0] = make_float4(y0.x, y0.y, y1.x, y1.y);
            float v0 = y0.x + y1.x, v1 = y0.x*y0.x + y1.x*y1.x;
            float v2 = y0.y + y1.y, v3 = y0.y*y0.y + y1.y*y1.y;
            #pragma unroll
            for (int off = 16; off; off >>= 1) {
                v0 += __shfl_xor_sync(0xffffffffu, v0, off);
                v1 += __shfl_xor_sync(0xffffffffu, v1, off);
                v2 += __shfl_xor_sync(0xffffffffu, v2, off);
                v3 += __shfl_xor_sync(0xffffffffu, v3, off);
            }
            if (n == 0) {
                atomicAdd(&g_stats1[o], v0);
                atomicAdd(&g_stats1[96+o], v1);
                atomicAdd(&g_stats1[192+o], v2);
                atomicAdd(&g_stats1[288+o], v3);
            }
        }
    }
}

// ---------------- finalize BN params ----------------
__global__ void k_bnfin(int which,
    const float* __restrict__ gr, const float* __restrict__ br,
    const float* __restrict__ gi, const float* __restrict__ bi)
{
    int c = threadIdx.x;
    if (c >= DIM) return;
    const float* s = which ? g_stats2 : g_stats1;
    float* o = which ? g_bn2 : g_bn1;
    const float invN = 1.0f / (float)HW;
    float mu = s[c]*invN;
    float var = s[96+c]*invN - mu*mu;
    float sc = gr[c]*rsqrtf(var + 1e-5f);
    o[c] = sc; o[96+c] = br[c] - mu*sc;
    mu = s[192+c]*invN;
    var = s[288+c]*invN - mu*mu;
    sc = gi[c]*rsqrtf(var + 1e-5f);
    o[192+c] = sc; o[288+c] = bi[c] - mu*sc;
}

// ---------------- mlp1: BN1-apply + GEMM + cgelu -> g_hid (64 px) ----------
#define MLP1_SMEM (21888*4)
__global__ __launch_bounds__(384, 2) void k_mlp1()
{
    extern __shared__ float sm[];
    const int SXP = 9216, SBN = 21504;
    int tid = threadIdx.x;
    int p0 = blockIdx.x * 64;
    int n = tid & 31, og = tid >> 5;
    float2* wslot = (float2*)sm + og*384;

    if (tid < 384) sm[SBN + tid] = g_bn1[tid];
    __syncthreads();

    for (int idx = tid; idx < 3072; idx += 384) {
        int c = idx >> 5, pp2 = (idx & 31) << 1;
        float4 yp = *(const float4*)(g_y_p + c*HW + p0 + pp2);
        float sr = sm[SBN + c], hr = sm[SBN + 96 + c];
        float si = sm[SBN + 192 + c], hi = sm[SBN + 288 + c];
        ((float4*)(sm + SXP))[idx] = make_float4(
            yp.x*sr + hr, yp.y*si + hi, yp.z*sr + hr, yp.w*si + hi);
    }
    __syncthreads();

    for (int ch = 0; ch < 8; ch++) {
        int o0 = og*32 + ch*4;
        __syncwarp();
        stage96f2(g_wf2 + W1OFF + o0*96, wslot, n);
        __syncwarp();
        ull S[8] = {0,0,0,0,0,0,0,0}, T[8] = {0,0,0,0,0,0,0,0};
        gemm96_2p(sm, SXP, n, wslot, S, T);
        #pragma unroll
        for (int l = 0; l < 4; l++) {
            float2 a = cmb(S[l], T[l]);
            float2 b = cmb(S[4+l], T[4+l]);
            float mga = sqrtf(a.x*a.x + a.y*a.y);
            float fa = 0.5f*mga*(1.0f + erff(mga*0.70710678118654752f)) / (mga + 1e-8f);
            float mgb = sqrtf(b.x*b.x + b.y*b.y);
            float fb = 0.5f*mgb*(1.0f + erff(mgb*0.70710678118654752f)) / (mgb + 1e-8f);
            ((float4*)(g_hid + (o0+l)*HW + p0))[n] =
                make_float4(a.x*fa, a.y*fa, b.x*fb, b.y*fb);
        }
    }
}

// ---------------- mlp2: hidden GEMM + residual + BN2 stats (64 px) --------
#define MLP2_SMEM (21888*4)
__global__ __launch_bounds__(384, 2) void k_mlp2()
{
    extern __shared__ float sm[];
    const int SH = 9216, SBN = 21504;
    int tid = threadIdx.x;
    int p0 = blockIdx.x * 64;
    int n = tid & 31, og = tid >> 5;
    float2* wslot = (float2*)sm + og*384;

    if (tid < 384) sm[SBN + tid] = g_bn1[tid];

    for (int ch = 0; ch < 2; ch++) {
        int o0 = og*8 + ch*4;
        ull S[8] = {0,0,0,0,0,0,0,0}, T[8] = {0,0,0,0,0,0,0,0};
        for (int cb = 0; cb < 4; cb++) {
            __syncthreads();
            for (int idx = tid; idx < 3072; idx += 384) {
                int c = idx >> 5, pp2 = (idx & 31) << 1;
                ((float4*)(sm + SH))[idx] =
                    *(const float4*)(g_hid + (cb*96 + c)*HW + p0 + pp2);
            }
            const float2* src = g_wf2 + W2OFF + o0*384 + cb*96;
            #pragma unroll
            for (int l = 0; l < 4; l++)
                for (int i = n; i < 96; i += 32) wslot[l*96 + i] = src[l*384 + i];
            __syncthreads();
            gemm96_2p(sm, SH, n, wslot, S, T);
        }
        #pragma unroll
        for (int l = 0; l < 4; l++) {
            int o = o0 + l;
            int g = o*HW + p0 + 2*n;
            float2 a = cmb(S[l], T[l]);
            float2 b = cmb(S[4+l], T[4+l]);
            float4 yv = ((const float4*)(g_y_p + g))[0];
            float scr = sm[SBN + o], shr = sm[SBN + 96 + o];
            float sci = sm[SBN + 192 + o], shi = sm[SBN + 288 + o];
            float2 t0 = make_float2(yv.x*scr + shr + a.x, yv.y*sci + shi + a.y);
            float2 t1 = make_float2(yv.z*scr + shr + b.x, yv.w*sci + shi + b.y);
            ((float4*)(g_t_p + g))[0] = make_float4(t0.x, t0.y, t1.x, t1.y);
            float v0 = t0.x + t1.x, v1 = t0.x*t0.x + t1.x*t1.x;
            float v2 = t0.y + t1.y, v3 = t0.y*t0.y + t1.y*t1.y;
            #pragma unroll
            for (int off = 16; off; off >>= 1) {
                v0 += __shfl_xor_sync(0xffffffffu, v0, off);
                v1 += __shfl_xor_sync(0xffffffffu, v1, off);
                v2 += __shfl_xor_sync(0xffffffffu, v2, off);
                v3 += __shfl_xor_sync(0xffffffffu, v3, off);
            }
            if (n == 0) {
                atomicAdd(&g_stats2[o], v0);
                atomicAdd(&g_stats2[96+o], v1);
                atomicAdd(&g_stats2[192+o], v2);
                atomicAdd(&g_stats2[288+o], v3);
            }
        }
    }
}

// ---------------- BN2-apply -> output (2 px / thread) ----------------
__global__ void k_out(float* __restrict__ out) {
    int idx = blockIdx.x*256 + threadIdx.x;
    if (idx >= DIM*HW/2) return;
    int i2 = idx << 1;
    int c = i2 / HW;
    float4 t = *(const float4*)(g_t_p + i2);
    float scr = g_bn2[c], shr = g_bn2[96+c];
    float sci = g_bn2[192+c], shi = g_bn2[288+c];
    *(float2*)(out + i2)          = make_float2(t.x*scr + shr, t.z*scr + shr);
    *(float2*)(out + DIM*HW + i2) = make_float2(t.y*sci + shi, t.w*sci + shi);
}

// ---------------- launch ----------------
extern "C" void kernel_launch(void* const* d_in, const int* in_sizes, int n_in,
                              void* d_out, int out_size)
{
    const float* xr   = (const float*)d_in[0];
    const float* xi   = (const float*)d_in[1];
    const float* qwr  = (const float*)d_in[2];
    const float* qwi  = (const float*)d_in[3];
    const float* pwr  = (const float*)d_in[4];
    const float* pwi  = (const float*)d_in[5];
    const float* rel  = (const float*)d_in[6];
    const float* w1r  = (const float*)d_in[7];
    const float* w1i  = (const float*)d_in[8];
    const float* w2r  = (const float*)d_in[9];
    const float* w2i  = (const float*)d_in[10];
    const float* n1gr = (const float*)d_in[11];
    const float* n1br = (const float*)d_in[12];
    const float* n1gi = (const float*)d_in[13];
    const float* n1bi = (const float*)d_in[14];
    const float* n2gr = (const float*)d_in[15];
    const float* n2br = (const float*)d_in[16];
    const float* n2gi = (const float*)d_in[17];
    const float* n2bi = (const float*)d_in[18];

    cudaFuncSetAttribute(k_qkv,     cudaFuncAttributeMaxDynamicSharedMemorySize, QKV_SMEM);
    cudaFuncSetAttribute(k_attnmid, cudaFuncAttributeMaxDynamicSharedMemorySize, AT_SMEM);
    cudaFuncSetAttribute(k_cproj,   cudaFuncAttributeMaxDynamicSharedMemorySize, CPROJ_SMEM);
    cudaFuncSetAttribute(k_mlp1,    cudaFuncAttributeMaxDynamicSharedMemorySize, MLP1_SMEM);
    cudaFuncSetAttribute(k_mlp2,    cudaFuncAttributeMaxDynamicSharedMemorySize, MLP2_SMEM);

    void *pfd, *ps1, *ps2;
    cudaGetSymbolAddress(&pfd, g_fold_p);
    cudaGetSymbolAddress(&ps1, g_stats1);
    cudaGetSymbolAddress(&ps2, g_stats2);
    cudaMemsetAsync(pfd, 0, sizeof(float2)*DIM*HW);
    cudaMemsetAsync(ps1, 0, sizeof(float)*4*DIM);
    cudaMemsetAsync(ps2, 0, sizeof(float)*4*DIM);

    k_pack<<<(NWTOT + 255)/256, 256>>>(qwr, qwi, pwr, pwi, w1r, w1i, w2r, w2i);
    k_qkv<<<HW/64, 384, QKV_SMEM>>>(xr, xi);
    k_attnmid<<<2*NWIN, 256, AT_SMEM>>>(rel);
    k_cproj<<<HW/64, 384, CPROJ_SMEM>>>(xr, xi);
    k_bnfin<<<1, 128>>>(0, n1gr, n1br, n1gi, n1bi);
    k_mlp1<<<HW/64, 384, MLP1_SMEM>>>();
    k_mlp2<<<HW/64, 384, MLP2_SMEM>>>();
    k_bnfin<<<1, 128>>>(1, n2gr, n2br, n2gi, n2bi);
    k_out<<<(DIM*HW/2 + 255)/256, 256>>>((float*)d_out);
}